// round 1
// baseline (speedup 1.0000x reference)
#include <cuda_runtime.h>
#include <mma.h>
#include <math.h>

using namespace nvcuda;

// Problem constants
constexpr int NB   = 2;
constexpr int NH   = 16;
constexpr int SEQ  = 2048;
constexpr int HD   = 128;
constexpr int HIDN = 2048;   // NH*HD
constexpr int QKVN = 6144;   // 3*HIDN

// Scratch (static device memory; allocation APIs are forbidden)
__device__ float g_q[(size_t)NB * NH * SEQ * HD];
__device__ float g_k[(size_t)NB * NH * SEQ * HD];
__device__ float g_v[(size_t)NB * NH * SEQ * HD];
__device__ float g_ctx[(size_t)NB * SEQ * HIDN];

__device__ __forceinline__ float tf32r(float x) { return wmma::__float_to_tf32(x); }

// ---------------------------------------------------------------------------
// tf32 GEMM: C[M,K=2048] x B[K,N].  MODE 0: qkv (scatter to g_q/g_k/g_v with
// head-split + transpose).  MODE 1: dense (g_ctx @ W_dense -> out).
// Block tile 128x128, k-tile 32, 8 warps each computing 64x32 via 4x2 wmma
// m16n16k8 tf32 fragments. Inputs are rounded to tf32 once on the smem store.
// ---------------------------------------------------------------------------
template <int MODE>
__global__ void __launch_bounds__(256) gemm_tf32(const float* __restrict__ A,
                                                 const float* __restrict__ Bw,
                                                 float* __restrict__ Cout)
{
    constexpr int N   = (MODE == 0) ? QKVN : HIDN;
    constexpr int LDA = HIDN;

    __shared__ __align__(16) float As[128 * 36];
    __shared__ __align__(16) float Bs[32 * 132];

    const int tid = threadIdx.x;
    const int wid = tid >> 5;
    const int wm  = wid >> 2;    // 0..1
    const int wn  = wid & 3;     // 0..3
    const int m0  = blockIdx.y * 128;
    const int n0  = blockIdx.x * 128;

    const float* Ap = (MODE == 0) ? A : g_ctx;

    wmma::fragment<wmma::accumulator, 16, 16, 8, float> acc[4][2];
#pragma unroll
    for (int i = 0; i < 4; i++)
#pragma unroll
        for (int j = 0; j < 2; j++) wmma::fill_fragment(acc[i][j], 0.0f);

    for (int k0 = 0; k0 < HIDN; k0 += 32) {
        // A tile: 128x32
#pragma unroll
        for (int it = 0; it < 4; it++) {
            int idx = tid + it * 256;              // 0..1023
            int r = idx >> 3, c = (idx & 7) * 4;
            float4 v = *(const float4*)&Ap[(size_t)(m0 + r) * LDA + k0 + c];
            v.x = tf32r(v.x); v.y = tf32r(v.y); v.z = tf32r(v.z); v.w = tf32r(v.w);
            *(float4*)&As[r * 36 + c] = v;
        }
        // B tile: 32x128
#pragma unroll
        for (int it = 0; it < 4; it++) {
            int idx = tid + it * 256;              // 0..1023
            int r = idx >> 5, c = (idx & 31) * 4;
            float4 v = *(const float4*)&Bw[(size_t)(k0 + r) * N + n0 + c];
            v.x = tf32r(v.x); v.y = tf32r(v.y); v.z = tf32r(v.z); v.w = tf32r(v.w);
            *(float4*)&Bs[r * 132 + c] = v;
        }
        __syncthreads();

#pragma unroll
        for (int ks = 0; ks < 4; ks++) {
            wmma::fragment<wmma::matrix_a, 16, 16, 8, wmma::precision::tf32, wmma::row_major> af[4];
            wmma::fragment<wmma::matrix_b, 16, 16, 8, wmma::precision::tf32, wmma::row_major> bf[2];
#pragma unroll
            for (int i = 0; i < 4; i++)
                wmma::load_matrix_sync(af[i], &As[(wm * 64 + i * 16) * 36 + ks * 8], 36);
#pragma unroll
            for (int j = 0; j < 2; j++)
                wmma::load_matrix_sync(bf[j], &Bs[(ks * 8) * 132 + wn * 32 + j * 16], 132);
#pragma unroll
            for (int i = 0; i < 4; i++)
#pragma unroll
                for (int j = 0; j < 2; j++)
                    wmma::mma_sync(acc[i][j], af[i], bf[j], acc[i][j]);
        }
        __syncthreads();
    }

    if (MODE == 0) {
        // n-tile index determines head + q/k/v section (384 = 3*128)
        int sec  = blockIdx.x;
        int head = sec / 3;
        int typ  = sec % 3;
        int b    = m0 >> 11;        // m rows are contiguous s within one batch
        int s0   = m0 & (SEQ - 1);
        float* base = (typ == 0 ? g_q : (typ == 1 ? g_k : g_v)) +
                      ((size_t)(b * NH + head) * SEQ + s0) * HD;
#pragma unroll
        for (int i = 0; i < 4; i++)
#pragma unroll
            for (int j = 0; j < 2; j++)
                wmma::store_matrix_sync(base + (size_t)(wm * 64 + i * 16) * HD + wn * 32 + j * 16,
                                        acc[i][j], HD, wmma::mem_row_major);
    } else {
#pragma unroll
        for (int i = 0; i < 4; i++)
#pragma unroll
            for (int j = 0; j < 2; j++)
                wmma::store_matrix_sync(Cout + (size_t)(m0 + wm * 64 + i * 16) * HIDN +
                                            n0 + wn * 32 + j * 16,
                                        acc[i][j], HIDN, wmma::mem_row_major);
    }
}

// ---------------------------------------------------------------------------
// xpos RoPE on first 32 dims of q and k. One thread per (b,h,s,j) pair, j<16.
// Caches computed on the fly in double precision (matches fp32 jnp reference
// to ~1e-7).
// ---------------------------------------------------------------------------
__global__ void __launch_bounds__(256) rope_kernel()
{
    int idx = blockIdx.x * 256 + threadIdx.x;   // < 2*16*2048*16 = 1048576
    int j  = idx & 15;
    int s  = (idx >> 4) & (SEQ - 1);
    int bh = idx >> 15;
    size_t base = ((size_t)bh * SEQ + s) * HD;

    double invf = exp(-(double)j / 16.0 * 9.210340371976184);  // 10000^(-j/16)
    double f = (double)s * invf;
    double sn, c;
    sincos(f, &sn, &c);
    double scj = (2.0 * j + 0.4 * 32.0) / (1.4 * 32.0);
    double pw  = ((double)s - 1024.0) / 512.0;
    double sc  = pow(scj, pw);

    float cq = (float)(c * sc),  sq = (float)(sn * sc);
    float ck = (float)(c / sc),  sk = (float)(sn / sc);

    float a = g_q[base + j], b = g_q[base + j + 16];
    g_q[base + j]      = a * cq - b * sq;
    g_q[base + j + 16] = b * cq + a * sq;

    a = g_k[base + j]; b = g_k[base + j + 16];
    g_k[base + j]      = a * ck - b * sk;
    g_k[base + j + 16] = b * ck + a * sk;
}

// ---------------------------------------------------------------------------
// Flash attention, causal, tf32 tensor cores for both QK^T and PV.
// One CTA per (b, h, 64-row q tile); 256 threads (8 warps).
//   S phase : warp grid 4x2 over 64x64 (warp tile 16x32)
//   softmax : one warp per 8 rows, streaming m/l/alpha in smem
//   PV phase: warp grid 4x2 over 64x128 (warp tile 16x64); O lives in smem,
//             round-tripped through accumulator fragments so the per-row
//             alpha rescale can be done with known addressing.
// ---------------------------------------------------------------------------
__global__ void __launch_bounds__(256) flash_attn(const float* __restrict__ amask)
{
    extern __shared__ __align__(16) float sm[];
    float* Qs   = sm;                  // 64*132
    float* Ks   = Qs + 64 * 132;       // 64*132
    float* Vs   = Ks + 64 * 132;       // 64*132
    float* Ps   = Vs + 64 * 132;       // 64*68
    float* Os   = Ps + 64 * 68;        // 64*132
    float* mrow = Os + 64 * 132;       // 64
    float* lrow = mrow + 64;           // 64
    float* arow = lrow + 64;           // 64

    const int tid  = threadIdx.x;
    const int wid  = tid >> 5;
    const int lane = tid & 31;
    const int qt   = blockIdx.x;
    const int h    = blockIdx.y;
    const int b    = blockIdx.z;
    const int bh   = b * NH + h;

    const float* qg = g_q + ((size_t)bh * SEQ + qt * 64) * HD;
    const float* am = amask + (size_t)b * SEQ;
    const float scale = 0.08838834764831845f;   // 1/sqrt(128)

    // Load Q (tf32-rounded) and zero O
    for (int idx = tid; idx < 64 * 32; idx += 256) {
        int r = idx >> 5, c = (idx & 31) * 4;
        float4 v = *(const float4*)&qg[r * HD + c];
        v.x = tf32r(v.x); v.y = tf32r(v.y); v.z = tf32r(v.z); v.w = tf32r(v.w);
        *(float4*)&Qs[r * 132 + c] = v;
        *(float4*)&Os[r * 132 + c] = make_float4(0.f, 0.f, 0.f, 0.f);
    }
    if (tid < 64) { mrow[tid] = -3.0e38f; lrow[tid] = 0.0f; }
    __syncthreads();

    for (int kt = 0; kt <= qt; kt++) {
        const float* kg = g_k + ((size_t)bh * SEQ + kt * 64) * HD;
        const float* vg = g_v + ((size_t)bh * SEQ + kt * 64) * HD;
        for (int idx = tid; idx < 64 * 32; idx += 256) {
            int r = idx >> 5, c = (idx & 31) * 4;
            float4 kv = *(const float4*)&kg[r * HD + c];
            kv.x = tf32r(kv.x); kv.y = tf32r(kv.y); kv.z = tf32r(kv.z); kv.w = tf32r(kv.w);
            *(float4*)&Ks[r * 132 + c] = kv;
            float4 vv = *(const float4*)&vg[r * HD + c];
            vv.x = tf32r(vv.x); vv.y = tf32r(vv.y); vv.z = tf32r(vv.z); vv.w = tf32r(vv.w);
            *(float4*)&Vs[r * 132 + c] = vv;
        }
        __syncthreads();

        // ---- S = Q K^T (64x64), warp tile 16x32 ----
        {
            const int wm = wid >> 1, wn = wid & 1;
            wmma::fragment<wmma::accumulator, 16, 16, 8, float> sacc[2];
            wmma::fill_fragment(sacc[0], 0.0f);
            wmma::fill_fragment(sacc[1], 0.0f);
#pragma unroll
            for (int ks = 0; ks < 16; ks++) {
                wmma::fragment<wmma::matrix_a, 16, 16, 8, wmma::precision::tf32, wmma::row_major> af;
                wmma::load_matrix_sync(af, &Qs[(wm * 16) * 132 + ks * 8], 132);
#pragma unroll
                for (int j = 0; j < 2; j++) {
                    wmma::fragment<wmma::matrix_b, 16, 16, 8, wmma::precision::tf32, wmma::col_major> bf;
                    wmma::load_matrix_sync(bf, &Ks[(wn * 32 + j * 16) * 132 + ks * 8], 132);
                    wmma::mma_sync(sacc[j], af, bf, sacc[j]);
                }
            }
#pragma unroll
            for (int j = 0; j < 2; j++)
                wmma::store_matrix_sync(&Ps[(wm * 16) * 68 + wn * 32 + j * 16], sacc[j], 68,
                                        wmma::mem_row_major);
        }
        __syncthreads();

        // ---- streaming softmax: warp w handles rows w*8 .. w*8+7 ----
#pragma unroll
        for (int r8 = 0; r8 < 8; r8++) {
            int r    = wid * 8 + r8;
            int qpos = qt * 64 + r;
            int c1 = lane, c2 = lane + 32;
            int kp1 = kt * 64 + c1, kp2 = kt * 64 + c2;
            float s1 = Ps[r * 68 + c1] * scale + am[kp1];
            float s2 = Ps[r * 68 + c2] * scale + am[kp2];
            if (kp1 > qpos) s1 = -1.0e30f;
            if (kp2 > qpos) s2 = -1.0e30f;
            float mx = fmaxf(s1, s2);
#pragma unroll
            for (int o = 16; o > 0; o >>= 1) mx = fmaxf(mx, __shfl_xor_sync(0xffffffffu, mx, o));
            float mold = mrow[r];
            float mnew = fmaxf(mold, mx);
            float p1 = __expf(s1 - mnew);
            float p2 = __expf(s2 - mnew);
            Ps[r * 68 + c1] = tf32r(p1);
            Ps[r * 68 + c2] = tf32r(p2);
            float ps = p1 + p2;
#pragma unroll
            for (int o = 16; o > 0; o >>= 1) ps += __shfl_xor_sync(0xffffffffu, ps, o);
            if (lane == 0) {
                float alpha = __expf(mold - mnew);
                lrow[r] = lrow[r] * alpha + ps;
                mrow[r] = mnew;
                arow[r] = alpha;
            }
        }
        __syncthreads();

        // ---- rescale O by alpha(row) ----
        for (int idx = tid; idx < 64 * 128; idx += 256) {
            int r = idx >> 7, c = idx & 127;
            Os[r * 132 + c] *= arow[r];
        }
        __syncthreads();

        // ---- O += P V (64x128), warp tile 16x64 ----
        {
            const int wm = wid >> 1, wn = wid & 1;
            wmma::fragment<wmma::accumulator, 16, 16, 8, float> oacc[4];
#pragma unroll
            for (int j = 0; j < 4; j++)
                wmma::load_matrix_sync(oacc[j], &Os[(wm * 16) * 132 + wn * 64 + j * 16], 132,
                                       wmma::mem_row_major);
#pragma unroll
            for (int ks = 0; ks < 8; ks++) {
                wmma::fragment<wmma::matrix_a, 16, 16, 8, wmma::precision::tf32, wmma::row_major> af;
                wmma::load_matrix_sync(af, &Ps[(wm * 16) * 68 + ks * 8], 68);
#pragma unroll
                for (int j = 0; j < 4; j++) {
                    wmma::fragment<wmma::matrix_b, 16, 16, 8, wmma::precision::tf32, wmma::row_major> bf;
                    wmma::load_matrix_sync(bf, &Vs[(ks * 8) * 132 + wn * 64 + j * 16], 132);
                    wmma::mma_sync(oacc[j], af, bf, oacc[j]);
                }
            }
#pragma unroll
            for (int j = 0; j < 4; j++)
                wmma::store_matrix_sync(&Os[(wm * 16) * 132 + wn * 64 + j * 16], oacc[j], 132,
                                        wmma::mem_row_major);
        }
        __syncthreads();
    }

    // ---- write context: ctx[b][s][h*128 + d] ----
    float* outp = g_ctx + ((size_t)(b * SEQ + qt * 64)) * HIDN + h * HD;
    for (int idx = tid; idx < 64 * 128; idx += 256) {
        int r = idx >> 7, c = idx & 127;
        outp[(size_t)r * HIDN + c] = Os[r * 132 + c] / lrow[r];
    }
}

// ---------------------------------------------------------------------------
// Launch
// ---------------------------------------------------------------------------
extern "C" void kernel_launch(void* const* d_in, const int* in_sizes, int n_in,
                              void* d_out, int out_size)
{
    const float* hidden = (const float*)d_in[0];
    const float* amask  = (const float*)d_in[1];
    const float* wqkv   = (const float*)d_in[2];
    const float* wdense = (const float*)d_in[3];
    float* out = (float*)d_out;

    constexpr int FLASH_SMEM = (3 * 64 * 132 + 64 * 68 + 64 * 132 + 192) * 4; // 153344 B
    cudaFuncSetAttribute((const void*)flash_attn,
                         cudaFuncAttributeMaxDynamicSharedMemorySize, FLASH_SMEM);

    // 1) QKV projection -> g_q/g_k/g_v [B,H,S,D]
    gemm_tf32<0><<<dim3(QKVN / 128, (NB * SEQ) / 128), 256>>>(hidden, wqkv, nullptr);
    // 2) xpos rotary on first 32 dims of q,k
    rope_kernel<<<(NB * NH * SEQ * 16) / 256, 256>>>();
    // 3) causal flash attention -> g_ctx [B,S,H*D]
    flash_attn<<<dim3(SEQ / 64, NH, NB), 256, FLASH_SMEM>>>(amask);
    // 4) output projection -> d_out
    gemm_tf32<1><<<dim3(HIDN / 128, (NB * SEQ) / 128), 256>>>(nullptr, wdense, out);
}

// round 3
// speedup vs baseline: 1.3055x; 1.3055x over previous
#include <cuda_runtime.h>
#include <mma.h>
#include <math.h>

using namespace nvcuda;

// Problem constants
constexpr int NB   = 2;
constexpr int NH   = 16;
constexpr int SEQ  = 2048;
constexpr int HD   = 128;
constexpr int HIDN = 2048;   // NH*HD
constexpr int QKVN = 6144;   // 3*HIDN

// Scratch (static device memory; allocation APIs are forbidden)
__device__ float g_q[(size_t)NB * NH * SEQ * HD];
__device__ float g_k[(size_t)NB * NH * SEQ * HD];
__device__ float g_v[(size_t)NB * NH * SEQ * HD];
__device__ float g_ctx[(size_t)NB * SEQ * HIDN];

__device__ __forceinline__ float tf32r(float x) { return wmma::__float_to_tf32(x); }

__device__ __forceinline__ void cp_async16(float* dst, const float* src) {
    unsigned s = (unsigned)__cvta_generic_to_shared(dst);
    asm volatile("cp.async.cg.shared.global [%0], [%1], 16;" :: "r"(s), "l"(src));
}

// ---------------------------------------------------------------------------
// tf32 GEMM, cp.async double-buffered, L2-friendly m-group swizzle.
// Block tile 128x128, k-tile 32. 8 warps x (64x32) via 4x2 wmma m16n16k8.
// Inputs copied raw (cp.async); tf32 rounding applied on fragments.
// MODE 0: hidden @ W_qkv, epilogue scatters to g_q/g_k/g_v [B,H,S,D].
// MODE 1: g_ctx @ W_dense -> out.
// ---------------------------------------------------------------------------
template <int MODE>
__global__ void __launch_bounds__(256, 2) gemm_tf32(const float* __restrict__ A,
                                                    const float* __restrict__ Bw,
                                                    float* __restrict__ Cout)
{
    constexpr int N     = (MODE == 0) ? QKVN : HIDN;
    constexpr int LDA   = HIDN;
    constexpr int NUM_N = N / 128;
    constexpr int GM    = 8;                 // m-block group for L2 reuse
    constexpr int ASZ   = 128 * 36;          // per-stage A floats
    constexpr int BSZ   = 32 * 132;          // per-stage B floats

    extern __shared__ __align__(16) float sm[];
    float* As = sm;               // 2 stages
    float* Bs = sm + 2 * ASZ;     // 2 stages

    const int tid = threadIdx.x;
    const int wid = tid >> 5;
    const int wm  = wid >> 2;
    const int wn  = wid & 3;

    // swizzled block mapping: groups of GM m-blocks sweep all n-blocks
    const int bid   = blockIdx.x;
    const int perg  = GM * NUM_N;
    const int grp   = bid / perg;
    const int rem   = bid - grp * perg;
    const int n_idx = rem / GM;
    const int m_idx = grp * GM + (rem - n_idx * GM);
    const int m0 = m_idx * 128;
    const int n0 = n_idx * 128;

    const float* Ap = (MODE == 0) ? A : g_ctx;

    wmma::fragment<wmma::accumulator, 16, 16, 8, float> acc[4][2];
#pragma unroll
    for (int i = 0; i < 4; i++)
#pragma unroll
        for (int j = 0; j < 2; j++) wmma::fill_fragment(acc[i][j], 0.0f);

    auto issue = [&](int k0, int st) {
#pragma unroll
        for (int it = 0; it < 4; it++) {
            int idx = tid + it * 256;
            int r = idx >> 3, c = (idx & 7) * 4;
            cp_async16(&As[st * ASZ + r * 36 + c], &Ap[(size_t)(m0 + r) * LDA + k0 + c]);
        }
#pragma unroll
        for (int it = 0; it < 4; it++) {
            int idx = tid + it * 256;
            int r = idx >> 5, c = (idx & 31) * 4;
            cp_async16(&Bs[st * BSZ + r * 132 + c], &Bw[(size_t)(k0 + r) * N + n0 + c]);
        }
        asm volatile("cp.async.commit_group;");
    };

    issue(0, 0);

    constexpr int KT = HIDN / 32;   // 64 k-steps
    for (int kt = 0; kt < KT; kt++) {
        if (kt + 1 < KT) {
            issue((kt + 1) * 32, (kt + 1) & 1);
            asm volatile("cp.async.wait_group 1;");
        } else {
            asm volatile("cp.async.wait_group 0;");
        }
        __syncthreads();

        const float* Ab = &As[(kt & 1) * ASZ];
        const float* Bb = &Bs[(kt & 1) * BSZ];
#pragma unroll
        for (int ks = 0; ks < 4; ks++) {
            wmma::fragment<wmma::matrix_a, 16, 16, 8, wmma::precision::tf32, wmma::row_major> af[4];
            wmma::fragment<wmma::matrix_b, 16, 16, 8, wmma::precision::tf32, wmma::row_major> bf[2];
#pragma unroll
            for (int i = 0; i < 4; i++) {
                wmma::load_matrix_sync(af[i], &Ab[(wm * 64 + i * 16) * 36 + ks * 8], 36);
#pragma unroll
                for (int e = 0; e < af[i].num_elements; e++) af[i].x[e] = tf32r(af[i].x[e]);
            }
#pragma unroll
            for (int j = 0; j < 2; j++) {
                wmma::load_matrix_sync(bf[j], &Bb[(ks * 8) * 132 + wn * 32 + j * 16], 132);
#pragma unroll
                for (int e = 0; e < bf[j].num_elements; e++) bf[j].x[e] = tf32r(bf[j].x[e]);
            }
#pragma unroll
            for (int i = 0; i < 4; i++)
#pragma unroll
                for (int j = 0; j < 2; j++)
                    wmma::mma_sync(acc[i][j], af[i], bf[j], acc[i][j]);
        }
        __syncthreads();
    }

    if (MODE == 0) {
        int head = n_idx / 3;
        int typ  = n_idx % 3;
        int b    = m0 >> 11;
        int s0   = m0 & (SEQ - 1);
        float* base = (typ == 0 ? g_q : (typ == 1 ? g_k : g_v)) +
                      ((size_t)(b * NH + head) * SEQ + s0) * HD;
#pragma unroll
        for (int i = 0; i < 4; i++)
#pragma unroll
            for (int j = 0; j < 2; j++)
                wmma::store_matrix_sync(base + (size_t)(wm * 64 + i * 16) * HD + wn * 32 + j * 16,
                                        acc[i][j], HD, wmma::mem_row_major);
    } else {
#pragma unroll
        for (int i = 0; i < 4; i++)
#pragma unroll
            for (int j = 0; j < 2; j++)
                wmma::store_matrix_sync(Cout + (size_t)(m0 + wm * 64 + i * 16) * HIDN +
                                            n0 + wn * 32 + j * 16,
                                        acc[i][j], HIDN, wmma::mem_row_major);
    }
}

// ---------------------------------------------------------------------------
// xpos RoPE on first 32 dims of q and k (double precision caches on the fly)
// ---------------------------------------------------------------------------
__global__ void __launch_bounds__(256) rope_kernel()
{
    int idx = blockIdx.x * 256 + threadIdx.x;   // < 2*16*2048*16
    int j  = idx & 15;
    int s  = (idx >> 4) & (SEQ - 1);
    int bh = idx >> 15;
    size_t base = ((size_t)bh * SEQ + s) * HD;

    double invf = exp(-(double)j / 16.0 * 9.210340371976184);
    double f = (double)s * invf;
    double sn, c;
    sincos(f, &sn, &c);
    double scj = (2.0 * j + 0.4 * 32.0) / (1.4 * 32.0);
    double pw  = ((double)s - 1024.0) / 512.0;
    double sc  = pow(scj, pw);

    float cq = (float)(c * sc),  sq = (float)(sn * sc);
    float ck = (float)(c / sc),  sk = (float)(sn / sc);

    float a = g_q[base + j], b = g_q[base + j + 16];
    g_q[base + j]      = a * cq - b * sq;
    g_q[base + j + 16] = b * cq + a * sq;

    a = g_k[base + j]; b = g_k[base + j + 16];
    g_k[base + j]      = a * ck - b * sk;
    g_k[base + j + 16] = b * ck + a * sk;
}

// ---------------------------------------------------------------------------
// Flash attention v2, register-resident O, raw mma.sync m16n8k8 tf32.
// CTA = 128 threads (4 warps), q-tile 64 (16 rows/warp), k-tile 64.
// Fragment layouts (PTX ISA, m16n8k8.row.col):
//   g = lane>>2, t = lane&3
//   A (16x8): a0(g,t) a1(g+8,t) a2(g,t+4) a3(g+8,t+4)
//   B (8x8) : b0(k=t,n=g) b1(k=t+4,n=g)
//   C (16x8): c0(g,2t) c1(g,2t+1) c2(g+8,2t) c3(g+8,2t+1)
// P (C layout) -> A layout done with 8 shuffles per 16x8 tile (no smem trip).
// ---------------------------------------------------------------------------
__device__ __forceinline__ void mma_tf32_16x8x8(float* d, const unsigned* a,
                                                unsigned b0, unsigned b1)
{
    asm volatile(
        "mma.sync.aligned.m16n8k8.row.col.f32.tf32.tf32.f32 "
        "{%0,%1,%2,%3}, {%4,%5,%6,%7}, {%8,%9}, {%0,%1,%2,%3};\n"
        : "+f"(d[0]), "+f"(d[1]), "+f"(d[2]), "+f"(d[3])
        : "r"(a[0]), "r"(a[1]), "r"(a[2]), "r"(a[3]), "r"(b0), "r"(b1));
}

__global__ void __launch_bounds__(128, 2) flash_attn2(const float* __restrict__ amask)
{
    extern __shared__ __align__(16) float fsm[];
    float* Ks = fsm;              // 64*132
    float* Vs = fsm + 64 * 132;   // 64*132

    const int tid  = threadIdx.x;
    const int wid  = tid >> 5;
    const int lane = tid & 31;
    const int g    = lane >> 2;
    const int t    = lane & 3;
    const int qt   = gridDim.x - 1 - blockIdx.x;   // long CTAs first
    const int h    = blockIdx.y;
    const int b    = blockIdx.z;
    const int bh   = b * NH + h;
    const int wr   = wid * 16;

    const float scale = 0.08838834764831845f;   // 1/sqrt(128)
    const float* am = amask + (size_t)b * SEQ;

    // ---- stage Q through Ks, load A-fragments to regs ----
    const float* qg = g_q + ((size_t)bh * SEQ + qt * 64) * HD;
    for (int idx = tid; idx < 64 * 32; idx += 128) {
        int r = idx >> 5, c = (idx & 31) * 4;
        float4 v = *(const float4*)&qg[r * HD + c];
        v.x = tf32r(v.x); v.y = tf32r(v.y); v.z = tf32r(v.z); v.w = tf32r(v.w);
        *(float4*)&Ks[r * 132 + c] = v;
    }
    __syncthreads();
    unsigned qa[16][4];
#pragma unroll
    for (int kc = 0; kc < 16; kc++) {
        qa[kc][0] = __float_as_uint(Ks[(wr + g)     * 132 + kc * 8 + t]);
        qa[kc][1] = __float_as_uint(Ks[(wr + g + 8) * 132 + kc * 8 + t]);
        qa[kc][2] = __float_as_uint(Ks[(wr + g)     * 132 + kc * 8 + t + 4]);
        qa[kc][3] = __float_as_uint(Ks[(wr + g + 8) * 132 + kc * 8 + t + 4]);
    }

    float o[16][4];
#pragma unroll
    for (int i = 0; i < 16; i++)
#pragma unroll
        for (int j = 0; j < 4; j++) o[i][j] = 0.0f;
    float m0 = -3.0e38f, m1 = -3.0e38f, l0 = 0.0f, l1 = 0.0f;

    const int qp0 = qt * 64 + wr + g;
    const int qp1 = qp0 + 8;
    const int srcA = (lane & 28) | (t >> 1);
    const int srcB = srcA + 2;

    for (int kt = 0; kt <= qt; kt++) {
        __syncthreads();   // previous iteration's smem reads done
        const float* kg = g_k + ((size_t)bh * SEQ + kt * 64) * HD;
        const float* vg = g_v + ((size_t)bh * SEQ + kt * 64) * HD;
        for (int idx = tid; idx < 64 * 32; idx += 128) {
            int r = idx >> 5, c = (idx & 31) * 4;
            float4 kv = *(const float4*)&kg[r * HD + c];
            kv.x = tf32r(kv.x); kv.y = tf32r(kv.y); kv.z = tf32r(kv.z); kv.w = tf32r(kv.w);
            *(float4*)&Ks[r * 132 + c] = kv;
            float4 vv = *(const float4*)&vg[r * HD + c];
            vv.x = tf32r(vv.x); vv.y = tf32r(vv.y); vv.z = tf32r(vv.z); vv.w = tf32r(vv.w);
            *(float4*)&Vs[r * 132 + c] = vv;
        }
        __syncthreads();

        // ---- S = Q K^T : 8 n-tiles of 8 cols ----
        float sacc[8][4];
#pragma unroll
        for (int nt = 0; nt < 8; nt++)
#pragma unroll
            for (int e = 0; e < 4; e++) sacc[nt][e] = 0.0f;
#pragma unroll
        for (int kc = 0; kc < 16; kc++) {
#pragma unroll
            for (int nt = 0; nt < 8; nt++) {
                unsigned b0 = __float_as_uint(Ks[(nt * 8 + g) * 132 + kc * 8 + t]);
                unsigned b1 = __float_as_uint(Ks[(nt * 8 + g) * 132 + kc * 8 + t + 4]);
                mma_tf32_16x8x8(sacc[nt], qa[kc], b0, b1);
            }
        }

        // ---- softmax (streaming, per-row m/l in regs) ----
        const bool diag = (kt == qt);
        float mx0 = -3.0e38f, mx1 = -3.0e38f;
#pragma unroll
        for (int nt = 0; nt < 8; nt++) {
            int col = kt * 64 + nt * 8 + 2 * t;
            float a0 = am[col], a1 = am[col + 1];
            float s0 = sacc[nt][0] * scale + a0;
            float s1 = sacc[nt][1] * scale + a1;
            float s2 = sacc[nt][2] * scale + a0;
            float s3 = sacc[nt][3] * scale + a1;
            if (diag) {
                if (col     > qp0) s0 = -1.0e30f;
                if (col + 1 > qp0) s1 = -1.0e30f;
                if (col     > qp1) s2 = -1.0e30f;
                if (col + 1 > qp1) s3 = -1.0e30f;
            }
            sacc[nt][0] = s0; sacc[nt][1] = s1; sacc[nt][2] = s2; sacc[nt][3] = s3;
            mx0 = fmaxf(mx0, fmaxf(s0, s1));
            mx1 = fmaxf(mx1, fmaxf(s2, s3));
        }
        mx0 = fmaxf(mx0, __shfl_xor_sync(0xffffffffu, mx0, 1));
        mx0 = fmaxf(mx0, __shfl_xor_sync(0xffffffffu, mx0, 2));
        mx1 = fmaxf(mx1, __shfl_xor_sync(0xffffffffu, mx1, 1));
        mx1 = fmaxf(mx1, __shfl_xor_sync(0xffffffffu, mx1, 2));

        float mn0 = fmaxf(m0, mx0), mn1 = fmaxf(m1, mx1);
        float al0 = __expf(m0 - mn0), al1 = __expf(m1 - mn1);
        m0 = mn0; m1 = mn1;

        float ps0 = 0.0f, ps1 = 0.0f;
#pragma unroll
        for (int nt = 0; nt < 8; nt++) {
            float p0 = __expf(sacc[nt][0] - mn0);
            float p1 = __expf(sacc[nt][1] - mn0);
            float p2 = __expf(sacc[nt][2] - mn1);
            float p3 = __expf(sacc[nt][3] - mn1);
            sacc[nt][0] = p0; sacc[nt][1] = p1; sacc[nt][2] = p2; sacc[nt][3] = p3;
            ps0 += p0 + p1;
            ps1 += p2 + p3;
        }
        ps0 += __shfl_xor_sync(0xffffffffu, ps0, 1);
        ps0 += __shfl_xor_sync(0xffffffffu, ps0, 2);
        ps1 += __shfl_xor_sync(0xffffffffu, ps1, 1);
        ps1 += __shfl_xor_sync(0xffffffffu, ps1, 2);
        l0 = l0 * al0 + ps0;
        l1 = l1 * al1 + ps1;

        // ---- rescale register O by alpha ----
#pragma unroll
        for (int i = 0; i < 16; i++) {
            o[i][0] *= al0; o[i][1] *= al0;
            o[i][2] *= al1; o[i][3] *= al1;
        }

        // ---- O += P V : P tiles converted C->A layout via shuffles ----
#pragma unroll
        for (int kc = 0; kc < 8; kc++) {
            unsigned p0 = __float_as_uint(tf32r(sacc[kc][0]));
            unsigned p1 = __float_as_uint(tf32r(sacc[kc][1]));
            unsigned p2 = __float_as_uint(tf32r(sacc[kc][2]));
            unsigned p3 = __float_as_uint(tf32r(sacc[kc][3]));
            unsigned x0 = __shfl_sync(0xffffffffu, p0, srcA);
            unsigned x1 = __shfl_sync(0xffffffffu, p1, srcA);
            unsigned y0 = __shfl_sync(0xffffffffu, p2, srcA);
            unsigned y1 = __shfl_sync(0xffffffffu, p3, srcA);
            unsigned z0 = __shfl_sync(0xffffffffu, p0, srcB);
            unsigned z1 = __shfl_sync(0xffffffffu, p1, srcB);
            unsigned w0 = __shfl_sync(0xffffffffu, p2, srcB);
            unsigned w1 = __shfl_sync(0xffffffffu, p3, srcB);
            unsigned pa[4];
            pa[0] = (t & 1) ? x1 : x0;
            pa[1] = (t & 1) ? y1 : y0;
            pa[2] = (t & 1) ? z1 : z0;
            pa[3] = (t & 1) ? w1 : w0;
#pragma unroll
            for (int nt = 0; nt < 16; nt++) {
                unsigned b0 = __float_as_uint(Vs[(kc * 8 + t)     * 132 + nt * 8 + g]);
                unsigned b1 = __float_as_uint(Vs[(kc * 8 + t + 4) * 132 + nt * 8 + g]);
                mma_tf32_16x8x8(o[nt], pa, b0, b1);
            }
        }
    }

    // ---- normalize and write ctx[b][s][h*128+d] ----
    float inv0 = 1.0f / l0, inv1 = 1.0f / l1;
    float* outp = g_ctx + ((size_t)(b * SEQ + qt * 64 + wr)) * HIDN + h * HD;
#pragma unroll
    for (int nt = 0; nt < 16; nt++) {
        float2 v0 = make_float2(o[nt][0] * inv0, o[nt][1] * inv0);
        float2 v1 = make_float2(o[nt][2] * inv1, o[nt][3] * inv1);
        *(float2*)&outp[(size_t)g * HIDN + nt * 8 + 2 * t]       = v0;
        *(float2*)&outp[(size_t)(g + 8) * HIDN + nt * 8 + 2 * t] = v1;
    }
}

// ---------------------------------------------------------------------------
// Launch
// ---------------------------------------------------------------------------
extern "C" void kernel_launch(void* const* d_in, const int* in_sizes, int n_in,
                              void* d_out, int out_size)
{
    const float* hidden = (const float*)d_in[0];
    const float* amask  = (const float*)d_in[1];
    const float* wqkv   = (const float*)d_in[2];
    const float* wdense = (const float*)d_in[3];
    float* out = (float*)d_out;

    constexpr int GEMM_SMEM   = (2 * 128 * 36 + 2 * 32 * 132) * 4;   // 70656 B
    constexpr int FLASH_SMEM  = 2 * 64 * 132 * 4;                    // 67584 B

    cudaFuncSetAttribute((const void*)gemm_tf32<0>,
                         cudaFuncAttributeMaxDynamicSharedMemorySize, GEMM_SMEM);
    cudaFuncSetAttribute((const void*)gemm_tf32<1>,
                         cudaFuncAttributeMaxDynamicSharedMemorySize, GEMM_SMEM);
    cudaFuncSetAttribute((const void*)flash_attn2,
                         cudaFuncAttributeMaxDynamicSharedMemorySize, FLASH_SMEM);

    // 1) QKV projection -> g_q/g_k/g_v [B,H,S,D]   (32 m-blocks x 48 n-blocks)
    gemm_tf32<0><<<32 * 48, 256, GEMM_SMEM>>>(hidden, wqkv, nullptr);
    // 2) xpos rotary on first 32 dims of q,k
    rope_kernel<<<(NB * NH * SEQ * 16) / 256, 256>>>();
    // 3) causal flash attention -> g_ctx [B,S,H*D]
    flash_attn2<<<dim3(SEQ / 64, NH, NB), 128, FLASH_SMEM>>>(amask);
    // 4) output projection -> d_out                (32 m-blocks x 16 n-blocks)
    gemm_tf32<1><<<32 * 16, 256, GEMM_SMEM>>>(nullptr, wdense, out);
}